// round 10
// baseline (speedup 1.0000x reference)
#include <cuda_runtime.h>

// ---------------------------------------------------------------------------
// Scatter: one WARP per real atom in [atomBase, atomBase+atomCount).
// Crop-local frame: t = 2*p + 15 (the data-dependent box offset cancels
// analytically between translation and crop start). Crop window is [0, 31].
// Lanes cover the clipped (y,z) footprint with z fastest (coalesced atomics);
// each lane walks x serially using a per-warp exp table in smem.
// Mask e<10 is applied as pv > exp(-10).
__global__ void __launch_bounds__(256)
fm_scatter_kernel(const float* __restrict__ coords,
                  const int*   __restrict__ channel,
                  const float* __restrict__ radius,
                  int L, int atomBase, int atomCount,
                  float* __restrict__ acc) {
    __shared__ float s_vx[8 * 12];

    const int wgl  = (blockIdx.x * blockDim.x + threadIdx.x) >> 5;
    const int warp = (threadIdx.x >> 5);
    const int lane = threadIdx.x & 31;
    if (wgl >= atomCount) return;
    const int wg = atomBase + wgl;
    const int b  = wg / L;

    const float* p = coords + (size_t)wg * 3;
    const float px = p[0], py = p[1], pz = p[2];
    const int   ch = channel[wg];
    const float rad = radius[wg] * 1.41421356237309515f;   // RADIUS_SCALE

    const float rt    = rad * 2.0f;                  // radius / res
    const float denom = 0.8649f * rt * rt;           // 0.93^2 * rt^2
    const float inv   = 1.0f / denom;
    const float rcut  = sqrtf(10.0f * denom) + 2e-3f;

    // Crop-local transformed coordinates.
    const float tx = px * 2.0f + 15.0f;
    const float ty = py * 2.0f + 15.0f;
    const float tz = pz * 2.0f + 15.0f;
    const int   dx = (int)floorf(tx);
    const int   dy = (int)floorf(ty);
    const int   dz = (int)floorf(tz);

    // Per-dim clipped local voxel ranges: cube ∩ cutoff-box ∩ crop [0,31].
    const int x0 = max(max(dx - 4, 0),  (int)ceilf (tx - 0.25f - rcut));
    const int x1 = min(min(dx + 6, 31), (int)floorf(tx - 0.25f + rcut));
    const int y0 = max(max(dy - 4, 0),  (int)ceilf (ty - 0.25f - rcut));
    const int y1 = min(min(dy + 6, 31), (int)floorf(ty - 0.25f + rcut));
    const int z0 = max(max(dz - 4, 0),  (int)ceilf (tz - 0.25f - rcut));
    const int z1 = min(min(dz + 6, 31), (int)floorf(tz - 0.25f + rcut));

    const int nx = x1 - x0 + 1, ny = y1 - y0 + 1, nz = z1 - z0 + 1;
    if (nx <= 0 || ny <= 0 || nz <= 0) return;

    // Per-warp x exp table (filters above are warp-uniform).
    float* vxw = s_vx + warp * 12;
    if (lane < nx) {
        const float dd = tx - ((float)(x0 + lane) + 0.25f);
        vxw[lane] = __expf(-(dd * dd * inv));
    }
    __syncwarp();

    const int base = (((b * 5 + ch) * 32 + x0) << 10);
    const int total_yz = ny * nz;
    const unsigned magic = 65536u / (unsigned)nz + 1u;   // exact for t*nz < 65536

    for (int t = lane; t < total_yz; t += 32) {
        const int iyr = (int)(((unsigned)t * magic) >> 16);
        const int izr = t - iyr * nz;
        const int gyi = y0 + iyr, gzi = z0 + izr;

        const float ddy = ty - ((float)gyi + 0.25f);
        const float ddz = tz - ((float)gzi + 0.25f);
        const float eyz = (ddy * ddy + ddz * ddz) * inv;
        if (eyz >= 10.0f) continue;                  // whole x-run masked
        const float vyz = __expf(-eyz);

        int idx = base + (gyi << 5) + gzi;
#pragma unroll 4
        for (int xi = 0; xi < nx; ++xi, idx += 1024) {
            const float pv = vxw[xi] * vyz;
            if (pv > 4.5399931e-5f) {                // e < 10  <=>  pv > e^-10
                float val;
                if (pv > 0.03125f) {
                    val = __logf(1.0f - pv);
                } else {
                    // ln(1-p) = -p(1 + p(1/2 + p/3)), |err| < 2.5e-7
                    val = -pv * fmaf(pv, fmaf(pv, 0.33333333f, 0.5f), 1.0f);
                }
                atomicAdd(acc + idx, val);
            }
        }
    }
}

// ---------------------------------------------------------------------------
// Finalize: in-place out = 1 - exp(out); all-zero float4 fast path;
// 2 quads per thread (measured-best variant).
__global__ void fm_finalize_kernel(float4* __restrict__ out, int n4) {
    const int i0 = (blockIdx.x * blockDim.x + threadIdx.x) * 2;
#pragma unroll
    for (int k = 0; k < 2; ++k) {
        const int i = i0 + k;
        if (i >= n4) return;
        float4 v = out[i];
        if ((__float_as_uint(v.x) | __float_as_uint(v.y) |
             __float_as_uint(v.z) | __float_as_uint(v.w)) == 0u)
            continue;                                // untouched: stays zero
        v.x = 1.0f - __expf(v.x);
        v.y = 1.0f - __expf(v.y);
        v.z = 1.0f - __expf(v.z);
        v.w = 1.0f - __expf(v.w);
        out[i] = v;
    }
}

// ---------------------------------------------------------------------------
// Two-way batch-split pipeline: finalize(half A) overlaps scatter(half B).
extern "C" void kernel_launch(void* const* d_in, const int* in_sizes, int n_in,
                              void* d_out, int out_size) {
    const float* coords = (const float*)d_in[0];   // [B, L, 3]
    const int*   chan   = (const int*)  d_in[1];   // [B, L]
    const float* rad    = (const float*)d_in[2];   // [B, L]

    const int BL = in_sizes[1];                    // B * L = 16384
    const int B  = out_size / (5 * 32 * 32 * 32);  // 32
    const int L  = BL / B;                         // 512

    static cudaStream_t s1 = nullptr;
    static cudaEvent_t  evFork = nullptr, evScatA = nullptr, evDone = nullptr;
    if (s1 == nullptr) {
        cudaStreamCreateWithFlags(&s1, cudaStreamNonBlocking);
        cudaEventCreateWithFlags(&evFork,  cudaEventDisableTiming);
        cudaEventCreateWithFlags(&evScatA, cudaEventDisableTiming);
        cudaEventCreateWithFlags(&evDone,  cudaEventDisableTiming);
    }

    if (B & 1) {                                   // safety fallback: serial path
        const int n4 = out_size / 4;
        cudaMemsetAsync(d_out, 0, (size_t)out_size * sizeof(float));
        fm_scatter_kernel<<<(BL * 32 + 255) / 256, 256>>>(
            coords, chan, rad, L, 0, BL, (float*)d_out);
        fm_finalize_kernel<<<((n4 + 1) / 2 + 255) / 256, 256>>>((float4*)d_out, n4);
        return;
    }

    const int atomsHalf = BL / 2;                  // batches [0,B/2) vs [B/2,B)
    const int elemsHalf = out_size / 2;
    const int n4h       = elemsHalf / 4;
    float* outA = (float*)d_out;
    float* outB = outA + elemsHalf;

    const int sblocks = (atomsHalf * 32 + 255) / 256;
    const int fblocks = ((n4h + 1) / 2 + 255) / 256;

    // Fork s1 off the capture (default) stream.
    cudaEventRecord(evFork, 0);
    cudaStreamWaitEvent(s1, evFork, 0);

    // memsets for both halves run up front (B's overlaps A's scatter).
    cudaMemsetAsync(outA, 0, (size_t)elemsHalf * sizeof(float), 0);
    cudaMemsetAsync(outB, 0, (size_t)elemsHalf * sizeof(float), s1);

    // Chain A on the default stream.
    fm_scatter_kernel<<<sblocks, 256, 0, 0>>>(
        coords, chan, rad, L, 0, atomsHalf, (float*)d_out);
    cudaEventRecord(evScatA, 0);
    fm_finalize_kernel<<<fblocks, 256, 0, 0>>>((float4*)outA, n4h);

    // Chain B on s1: scatter B starts when scatter A is done (so finalize A
    // overlaps scatter B), then finalize B.
    cudaStreamWaitEvent(s1, evScatA, 0);
    fm_scatter_kernel<<<sblocks, 256, 0, s1>>>(
        coords, chan, rad, L, atomsHalf, atomsHalf, (float*)d_out);
    fm_finalize_kernel<<<fblocks, 256, 0, s1>>>((float4*)outB, n4h);

    // Join.
    cudaEventRecord(evDone, s1);
    cudaStreamWaitEvent(0, evDone, 0);
}

// round 11
// speedup vs baseline: 1.0515x; 1.0515x over previous
#include <cuda_runtime.h>

// ---------------------------------------------------------------------------
// Scatter: one WARP per real atom. Crop-local frame: t = 2*p + 15 (the data-
// dependent box offset cancels analytically). Crop window [0,31].
// Lanes cover the clipped (y, z-group-of-4) footprint; each lane walks x
// serially. Each surviving (x,y,zgroup) issues ONE red.global.add.v4.f32
// (16B-aligned: z groups start at multiples of 4). Entries outside [z0,z1]
// or below the e<10 mask contribute exactly 0.
__global__ void __launch_bounds__(256)
fm_scatter_kernel(const float* __restrict__ coords,
                  const int*   __restrict__ channel,
                  const float* __restrict__ radius,
                  int L, int BL,
                  float* __restrict__ acc) {
    __shared__ float s_vx [8 * 12];   // exp(-ex^2) per x
    __shared__ float s_vz [8 * 16];   // exp(-ez^2) per z (grouped by 4, padded 0)
    __shared__ float s_gm [8 * 4];    // per-z-group max of s_vz

    const int wg   = (blockIdx.x * blockDim.x + threadIdx.x) >> 5;
    const int warp = (threadIdx.x >> 5);
    const int lane = threadIdx.x & 31;
    if (wg >= BL) return;
    const int b = wg / L;

    const float* p = coords + (size_t)wg * 3;
    const float px = p[0], py = p[1], pz = p[2];
    const int   ch = channel[wg];
    const float rad = radius[wg] * 1.41421356237309515f;   // RADIUS_SCALE

    const float rt    = rad * 2.0f;                  // radius / res
    const float denom = 0.8649f * rt * rt;           // 0.93^2 * rt^2
    const float inv   = 1.0f / denom;
    const float rcut  = sqrtf(10.0f * denom) + 2e-3f;

    const float tx = px * 2.0f + 15.0f;
    const float ty = py * 2.0f + 15.0f;
    const float tz = pz * 2.0f + 15.0f;
    const int   dx = (int)floorf(tx);
    const int   dy = (int)floorf(ty);
    const int   dz = (int)floorf(tz);

    // Per-dim clipped local voxel ranges: cube ∩ cutoff-box ∩ crop [0,31].
    const int x0 = max(max(dx - 4, 0),  (int)ceilf (tx - 0.25f - rcut));
    const int x1 = min(min(dx + 6, 31), (int)floorf(tx - 0.25f + rcut));
    const int y0 = max(max(dy - 4, 0),  (int)ceilf (ty - 0.25f - rcut));
    const int y1 = min(min(dy + 6, 31), (int)floorf(ty - 0.25f + rcut));
    const int z0 = max(max(dz - 4, 0),  (int)ceilf (tz - 0.25f - rcut));
    const int z1 = min(min(dz + 6, 31), (int)floorf(tz - 0.25f + rcut));

    const int nx = x1 - x0 + 1, ny = y1 - y0 + 1, nz = z1 - z0 + 1;
    if (nx <= 0 || ny <= 0 || nz <= 0) return;

    const int zg0 = z0 & ~3;                         // first aligned z group
    const int ngz = (z1 >> 2) - (z0 >> 2) + 1;       // #groups of 4 (<= 4)

    const float thresh = 4.5399931e-5f;              // e^-10

    // Per-warp tables (filters above are warp-uniform).
    float* vxw = s_vx + warp * 12;
    float* vzw = s_vz + warp * 16;
    float* gmw = s_gm + warp * 4;

    float mvx = 0.0f, mvz = 0.0f;
    if (lane < nx) {
        const float dd = tx - ((float)(x0 + lane) + 0.25f);
        mvx = __expf(-(dd * dd * inv));
        vxw[lane] = mvx;
    }
    if (lane < ngz * 4) {
        const int z = zg0 + lane;
        float v = 0.0f;
        if (z >= z0 && z <= z1) {
            const float dd = tz - ((float)z + 0.25f);
            v = __expf(-(dd * dd * inv));
        }
        mvz = v;
        vzw[lane] = v;
    }
    __syncwarp();
    if (lane < ngz) {
        const float* g = vzw + lane * 4;
        gmw[lane] = fmaxf(fmaxf(g[0], g[1]), fmaxf(g[2], g[3]));
    }
#pragma unroll
    for (int o = 16; o; o >>= 1) {
        mvx = fmaxf(mvx, __shfl_xor_sync(0xFFFFFFFFu, mvx, o));
        mvz = fmaxf(mvz, __shfl_xor_sync(0xFFFFFFFFu, mvz, o));
    }
    const float vxzmax = mvx * mvz;
    __syncwarp();

    const int base = (((b * 5 + ch) * 32 + x0) << 10);
    const int total_t = ny * ngz;
    const unsigned magic = 65536u / (unsigned)ngz + 1u;  // exact for t*ngz < 65536

    for (int t = lane; t < total_t; t += 32) {
        const int iyr = (int)(((unsigned)t * magic) >> 16);
        const int izg = t - iyr * ngz;
        const int gyi = y0 + iyr;

        const float ddy = ty - ((float)gyi + 0.25f);
        const float vy  = __expf(-(ddy * ddy * inv));
        if (vy * vxzmax <= thresh) continue;         // whole column masked

        const float4 vz = *(const float4*)(vzw + izg * 4);
        const float  gm = gmw[izg];

        int idx = base + (gyi << 5) + zg0 + (izg << 2);
#pragma unroll 4
        for (int xi = 0; xi < nx; ++xi, idx += 1024) {
            const float w = vxw[xi] * vy;
            if (w * gm > thresh) {                   // >=1 entry survives
                float pv0 = w * vz.x, pv1 = w * vz.y, pv2 = w * vz.z, pv3 = w * vz.w;
                // ln(1-p) ~= -p(1 + p(1/2 + p/3)) for small p; exact-ish __logf else
                float v0 = -pv0 * fmaf(pv0, fmaf(pv0, 0.33333333f, 0.5f), 1.0f);
                float v1 = -pv1 * fmaf(pv1, fmaf(pv1, 0.33333333f, 0.5f), 1.0f);
                float v2 = -pv2 * fmaf(pv2, fmaf(pv2, 0.33333333f, 0.5f), 1.0f);
                float v3 = -pv3 * fmaf(pv3, fmaf(pv3, 0.33333333f, 0.5f), 1.0f);
                if (pv0 > 0.03125f) v0 = __logf(1.0f - pv0);
                if (pv1 > 0.03125f) v1 = __logf(1.0f - pv1);
                if (pv2 > 0.03125f) v2 = __logf(1.0f - pv2);
                if (pv3 > 0.03125f) v3 = __logf(1.0f - pv3);
                v0 = (pv0 > thresh) ? v0 : 0.0f;
                v1 = (pv1 > thresh) ? v1 : 0.0f;
                v2 = (pv2 > thresh) ? v2 : 0.0f;
                v3 = (pv3 > thresh) ? v3 : 0.0f;
                asm volatile(
                    "red.global.add.v4.f32 [%0], {%1, %2, %3, %4};"
                    :: "l"(acc + idx), "f"(v0), "f"(v1), "f"(v2), "f"(v3)
                    : "memory");
            }
        }
    }
}

// ---------------------------------------------------------------------------
// Finalize: in-place out = 1 - exp(out); all-zero float4 fast path;
// 2 quads per thread (measured-best variant).
__global__ void fm_finalize_kernel(float4* __restrict__ out, int n4) {
    const int i0 = (blockIdx.x * blockDim.x + threadIdx.x) * 2;
#pragma unroll
    for (int k = 0; k < 2; ++k) {
        const int i = i0 + k;
        if (i >= n4) return;
        float4 v = out[i];
        if ((__float_as_uint(v.x) | __float_as_uint(v.y) |
             __float_as_uint(v.z) | __float_as_uint(v.w)) == 0u)
            continue;                                // untouched: stays zero
        v.x = 1.0f - __expf(v.x);
        v.y = 1.0f - __expf(v.y);
        v.z = 1.0f - __expf(v.z);
        v.w = 1.0f - __expf(v.w);
        out[i] = v;
    }
}

// ---------------------------------------------------------------------------
extern "C" void kernel_launch(void* const* d_in, const int* in_sizes, int n_in,
                              void* d_out, int out_size) {
    const float* coords = (const float*)d_in[0];   // [B, L, 3]
    const int*   chan   = (const int*)  d_in[1];   // [B, L]
    const float* rad    = (const float*)d_in[2];   // [B, L]

    const int BL = in_sizes[1];                    // B * L = 16384
    const int n4 = out_size / 4;
    const int B  = out_size / (5 * 32 * 32 * 32);  // 32
    const int L  = BL / B;                         // 512

    // Zero the accumulator via the driver's memset path (graph memset node).
    cudaMemsetAsync(d_out, 0, (size_t)out_size * sizeof(float));

    const int sblocks = (BL * 32 + 255) / 256;     // one warp per real atom
    fm_scatter_kernel<<<sblocks, 256>>>(coords, chan, rad, L, BL, (float*)d_out);
    const int fblocks = ((n4 + 1) / 2 + 255) / 256;
    fm_finalize_kernel<<<fblocks, 256>>>((float4*)d_out, n4);
}

// round 12
// speedup vs baseline: 1.1481x; 1.0920x over previous
#include <cuda_runtime.h>

// ---------------------------------------------------------------------------
// Scatter: one WARP per real atom. Crop-local frame: t = 2*p + 15 (the data-
// dependent box offset cancels analytically). Crop window [0,31].
// Lanes cover the clipped (y, z-PAIR) footprint (pairs aligned to even z, 8B);
// each lane walks x serially using a per-warp exp table in smem. Each
// surviving (x,y,zpair) issues ONE red.global.add.v2.f32. Padded / masked
// entries contribute exactly 0.
__global__ void __launch_bounds__(256)
fm_scatter_kernel(const float* __restrict__ coords,
                  const int*   __restrict__ channel,
                  const float* __restrict__ radius,
                  int L, int BL,
                  float* __restrict__ acc) {
    __shared__ float s_vx[8 * 12];    // exp(-ex^2) per x
    __shared__ float s_vz[8 * 12];    // exp(-ez^2) per z, even-aligned, 0-padded
    __shared__ float s_pm[8 * 6];     // per-pair max of s_vz

    const int wg   = (blockIdx.x * blockDim.x + threadIdx.x) >> 5;
    const int warp = (threadIdx.x >> 5);
    const int lane = threadIdx.x & 31;
    if (wg >= BL) return;
    const int b = wg / L;

    const float* p = coords + (size_t)wg * 3;
    const float px = p[0], py = p[1], pz = p[2];
    const int   ch = channel[wg];
    const float rad = radius[wg] * 1.41421356237309515f;   // RADIUS_SCALE

    const float rt    = rad * 2.0f;                  // radius / res
    const float denom = 0.8649f * rt * rt;           // 0.93^2 * rt^2
    const float inv   = 1.0f / denom;
    const float rcut  = sqrtf(10.0f * denom) + 2e-3f;

    const float tx = px * 2.0f + 15.0f;
    const float ty = py * 2.0f + 15.0f;
    const float tz = pz * 2.0f + 15.0f;
    const int   dx = (int)floorf(tx);
    const int   dy = (int)floorf(ty);
    const int   dz = (int)floorf(tz);

    // Per-dim clipped local voxel ranges: cube ∩ cutoff-box ∩ crop [0,31].
    const int x0 = max(max(dx - 4, 0),  (int)ceilf (tx - 0.25f - rcut));
    const int x1 = min(min(dx + 6, 31), (int)floorf(tx - 0.25f + rcut));
    const int y0 = max(max(dy - 4, 0),  (int)ceilf (ty - 0.25f - rcut));
    const int y1 = min(min(dy + 6, 31), (int)floorf(ty - 0.25f + rcut));
    const int z0 = max(max(dz - 4, 0),  (int)ceilf (tz - 0.25f - rcut));
    const int z1 = min(min(dz + 6, 31), (int)floorf(tz - 0.25f + rcut));

    const int nx = x1 - x0 + 1, ny = y1 - y0 + 1, nz = z1 - z0 + 1;
    if (nx <= 0 || ny <= 0 || nz <= 0) return;

    const int zp0 = z0 & ~1;                         // first even z (8B-aligned pair)
    const int npz = (z1 >> 1) - (z0 >> 1) + 1;       // #pairs (<= 6)

    const float thresh = 4.5399931e-5f;              // e^-10

    // Per-warp tables (filters above are warp-uniform).
    float* vxw = s_vx + warp * 12;
    float* vzw = s_vz + warp * 12;
    float* pmw = s_pm + warp * 6;

    if (lane < nx) {
        const float dd = tx - ((float)(x0 + lane) + 0.25f);
        vxw[lane] = __expf(-(dd * dd * inv));
    }
    if (lane < npz * 2) {
        const int z = zp0 + lane;
        float v = 0.0f;
        if (z >= z0 && z <= z1) {
            const float dd = tz - ((float)z + 0.25f);
            v = __expf(-(dd * dd * inv));
        }
        vzw[lane] = v;
    }
    __syncwarp();
    if (lane < npz)
        pmw[lane] = fmaxf(vzw[lane * 2], vzw[lane * 2 + 1]);
    __syncwarp();

    const int base = (((b * 5 + ch) * 32 + x0) << 10);
    const int total_t = ny * npz;
    const unsigned magic = 65536u / (unsigned)npz + 1u; // exact for t*npz < 65536

    for (int t = lane; t < total_t; t += 32) {
        const int iyr = (int)(((unsigned)t * magic) >> 16);
        const int izp = t - iyr * npz;
        const int gyi = y0 + iyr;

        const float ddy = ty - ((float)gyi + 0.25f);
        const float vy  = __expf(-(ddy * ddy * inv));

        const float2 vz = *(const float2*)(vzw + izp * 2);
        const float  pm = pmw[izp] * vy;             // vy * max(vz0, vz1)

        int idx = base + (gyi << 5) + zp0 + (izp << 1);
#pragma unroll 4
        for (int xi = 0; xi < nx; ++xi, idx += 1024) {
            const float vx = vxw[xi];
            if (vx * pm > thresh) {                  // >=1 of the pair survives
                const float w   = vx * vy;
                const float pv0 = w * vz.x;
                const float pv1 = w * vz.y;
                // ln(1-p) ~= -p(1 + p(1/2 + p/3)) for small p; __logf else
                float v0 = -pv0 * fmaf(pv0, fmaf(pv0, 0.33333333f, 0.5f), 1.0f);
                float v1 = -pv1 * fmaf(pv1, fmaf(pv1, 0.33333333f, 0.5f), 1.0f);
                if (pv0 > 0.03125f) v0 = __logf(1.0f - pv0);
                if (pv1 > 0.03125f) v1 = __logf(1.0f - pv1);
                v0 = (pv0 > thresh) ? v0 : 0.0f;
                v1 = (pv1 > thresh) ? v1 : 0.0f;
                asm volatile(
                    "red.global.add.v2.f32 [%0], {%1, %2};"
                    :: "l"(acc + idx), "f"(v0), "f"(v1)
                    : "memory");
            }
        }
    }
}

// ---------------------------------------------------------------------------
// Finalize: in-place out = 1 - exp(out); all-zero float4 fast path;
// 2 quads per thread (measured-best variant).
__global__ void fm_finalize_kernel(float4* __restrict__ out, int n4) {
    const int i0 = (blockIdx.x * blockDim.x + threadIdx.x) * 2;
#pragma unroll
    for (int k = 0; k < 2; ++k) {
        const int i = i0 + k;
        if (i >= n4) return;
        float4 v = out[i];
        if ((__float_as_uint(v.x) | __float_as_uint(v.y) |
             __float_as_uint(v.z) | __float_as_uint(v.w)) == 0u)
            continue;                                // untouched: stays zero
        v.x = 1.0f - __expf(v.x);
        v.y = 1.0f - __expf(v.y);
        v.z = 1.0f - __expf(v.z);
        v.w = 1.0f - __expf(v.w);
        out[i] = v;
    }
}

// ---------------------------------------------------------------------------
extern "C" void kernel_launch(void* const* d_in, const int* in_sizes, int n_in,
                              void* d_out, int out_size) {
    const float* coords = (const float*)d_in[0];   // [B, L, 3]
    const int*   chan   = (const int*)  d_in[1];   // [B, L]
    const float* rad    = (const float*)d_in[2];   // [B, L]

    const int BL = in_sizes[1];                    // B * L = 16384
    const int n4 = out_size / 4;
    const int B  = out_size / (5 * 32 * 32 * 32);  // 32
    const int L  = BL / B;                         // 512

    // Zero the accumulator via the driver's memset path (graph memset node).
    cudaMemsetAsync(d_out, 0, (size_t)out_size * sizeof(float));

    const int sblocks = (BL * 32 + 255) / 256;     // one warp per real atom
    fm_scatter_kernel<<<sblocks, 256>>>(coords, chan, rad, L, BL, (float*)d_out);
    const int fblocks = ((n4 + 1) / 2 + 255) / 256;
    fm_finalize_kernel<<<fblocks, 256>>>((float4*)d_out, n4);
}